// round 2
// baseline (speedup 1.0000x reference)
#include <cuda_runtime.h>
#include <cstdint>

// B=4096, A=128, RF=K=128, F=128, all fp32. out = mask * relu(resid @ w + node)
#define A_DIM     128
#define F_DIM     128
#define K_DIM     128
#define TILE_ROWS 64
#define KC        32

__global__ __launch_bounds__(256)
void blockend_kernel(const float* __restrict__ node,
                     const float* __restrict__ resid,
                     const float* __restrict__ w,
                     const int*   __restrict__ mol_i32,   // raw mol_slice bytes as int32 view
                     float* __restrict__ out)
{
    const int b    = blockIdx.x;
    const int row0 = blockIdx.y * TILE_ROWS;
    const int t    = threadIdx.x;

    // ---- robust mol_slice layout detection ----
    // int64 layout (little-endian), values < 2^31:
    //   i32 view: [M0, 0, 128, 0, M1, 0, 128, 0, ...]  -> i32[1]==0
    // int32 layout:
    //   i32 view: [M0, 128, M1, 128, ...]              -> i32[1]==128 (!=0)
    const bool is_i64 = (mol_i32[1] == 0);
    const int  M      = is_i64 ? mol_i32[4 * b] : mol_i32[2 * b];

    float* outp = out + ((size_t)b * A_DIM + row0) * F_DIM;

    // ---- fully masked tile: zero fill ----
    if (row0 >= M) {
        float4 z = make_float4(0.f, 0.f, 0.f, 0.f);
        float4* o4 = (float4*)outp;
        #pragma unroll
        for (int i = 0; i < (TILE_ROWS * F_DIM / 4) / 256; i++)
            o4[t + i * 256] = z;
        return;
    }

    __shared__ float ws[KC][F_DIM];        // ws[kk][f] = w[k0+kk][f]
    __shared__ float rs[TILE_ROWS][KC];    // rs[r][kk] = resid[row0+r][k0+kk]

    const float* residp = resid + ((size_t)b * A_DIM + row0) * K_DIM;

    const int tx = t & 31;    // col group: cols tx*4 .. tx*4+3
    const int ty = t >> 5;    // row group: rows ty*8 .. ty*8+7

    float acc[8][4];
    #pragma unroll
    for (int i = 0; i < 8; i++)
        #pragma unroll
        for (int j = 0; j < 4; j++) acc[i][j] = 0.f;

    for (int k0 = 0; k0 < K_DIM; k0 += KC) {
        if (k0) __syncthreads();

        // stage W chunk: 32 x 128 floats = 1024 float4, 4 per thread
        {
            const float4* wsrc = (const float4*)(w + (size_t)k0 * F_DIM);
            float4* wdst = (float4*)&ws[0][0];
            #pragma unroll
            for (int i = 0; i < 4; i++)
                wdst[t + i * 256] = wsrc[t + i * 256];
        }
        // stage residual chunk: 64 x 32 floats = 512 float4, 2 per thread
        {
            float4* rdst = (float4*)&rs[0][0];
            #pragma unroll
            for (int i = 0; i < 2; i++) {
                int f4 = t + i * 256;          // 0..511
                int r  = f4 >> 3;              // row 0..63
                int kg = f4 & 7;               // k-group 0..7
                rdst[f4] = *(const float4*)(residp + (size_t)r * K_DIM + k0 + kg * 4);
            }
        }
        __syncthreads();

        // compute: a = broadcast scalar per row, b = float4 of 4 cols
        #pragma unroll
        for (int kk = 0; kk < KC; kk++) {
            float4 bv = *(const float4*)&ws[kk][tx * 4];
            #pragma unroll
            for (int i = 0; i < 8; i++) {
                float a = rs[ty * 8 + i][kk];   // warp-broadcast (all lanes same addr)
                acc[i][0] = fmaf(a, bv.x, acc[i][0]);
                acc[i][1] = fmaf(a, bv.y, acc[i][1]);
                acc[i][2] = fmaf(a, bv.z, acc[i][2]);
                acc[i][3] = fmaf(a, bv.w, acc[i][3]);
            }
        }
    }

    // ---- epilogue: + node, relu, row mask, store ----
    const float* nodep = node + ((size_t)b * A_DIM + row0) * F_DIM;
    #pragma unroll
    for (int i = 0; i < 8; i++) {
        int r = ty * 8 + i;
        float4 o;
        if (row0 + r < M) {
            float4 nv = *(const float4*)(nodep + (size_t)r * F_DIM + tx * 4);
            o.x = fmaxf(acc[i][0] + nv.x, 0.f);
            o.y = fmaxf(acc[i][1] + nv.y, 0.f);
            o.z = fmaxf(acc[i][2] + nv.z, 0.f);
            o.w = fmaxf(acc[i][3] + nv.w, 0.f);
        } else {
            o = make_float4(0.f, 0.f, 0.f, 0.f);
        }
        *(float4*)(outp + (size_t)r * F_DIM + tx * 4) = o;
    }
}

extern "C" void kernel_launch(void* const* d_in, const int* in_sizes, int n_in,
                              void* d_out, int out_size) {
    // Size-based input identification (robust to metadata ordering):
    //   two big arrays (B*A*128 elems): first = node_features, second = residual_features
    //   small arrays: w (16384 fp32) and mol_slice (8192 int64 or 16384 int32-view)
    const float* node = nullptr;
    const float* res  = nullptr;
    const void*  wptr = nullptr;
    const void*  mptr = nullptr;

    for (int i = 0; i < n_in; i++) {
        if (in_sizes[i] >= (1 << 20)) {
            if (!node) node = (const float*)d_in[i];
            else if (!res) res = (const float*)d_in[i];
        }
    }
    // small inputs, in order: prefer first 16384 as w, remaining as mol_slice
    for (int i = 0; i < n_in; i++) {
        if (in_sizes[i] < (1 << 20)) {
            if (!wptr && in_sizes[i] == F_DIM * K_DIM) { wptr = d_in[i]; continue; }
            if (!mptr && d_in[i] != wptr) mptr = d_in[i];
        }
    }
    // fallback to dict order if anything unresolved
    if (!node) node = (const float*)d_in[0];
    if (!res)  res  = (const float*)d_in[1];
    if (!wptr) wptr = d_in[2];
    if (!mptr) mptr = d_in[3];

    float* out = (float*)d_out;
    int B = 0;
    for (int i = 0; i < n_in; i++)
        if (in_sizes[i] >= (1 << 20)) { B = in_sizes[i] / (A_DIM * F_DIM); break; }
    if (!B) B = 4096;

    dim3 grid(B, A_DIM / TILE_ROWS);   // (4096, 2)
    blockend_kernel<<<grid, 256>>>(node, res, (const float*)wptr,
                                   (const int*)mptr, out);
}